// round 14
// baseline (speedup 1.0000x reference)
#include <cuda_runtime.h>
#include <cuda_bf16.h>
#include <math.h>
#include <stdint.h>

#define BATCH   4
#define NTOK    8192
#define CH      256
#define HEADS   8
#define KQVROWS 768
#define NSPL    64
#define CCH     (NTOK / NSPL / 32)

#define SCALE_W 32.0f
#define INV_W   (1.0f / 32.0f)

// ---------------- scratch ----------------
__device__ uint8_t g_Wf8[KQVROWS * CH];                          // fp8 [Wk;Wq;Wv] * 32
__device__ uint8_t g_xT8[(size_t)BATCH * NTOK * CH];             // fp8 x^T [b][s][c]
__device__ __nv_bfloat16 g_kqvb[(size_t)BATCH * KQVROWS * NTOK]; // expK(0..255) Qn(256..511) V(512..767)
__device__ float g_ctxp[BATCH * HEADS * NSPL * 32 * 32];
__device__ float g_zp[BATCH * HEADS * NSPL * 32];
__device__ __nv_bfloat16 g_Mbf[BATCH * CH * CH];

// ---------------- helpers ----------------
__device__ __forceinline__ uint32_t smem_u32(const void* p) {
    return (uint32_t)__cvta_generic_to_shared(p);
}
__device__ __forceinline__ void ldsm_x4(uint32_t& r0, uint32_t& r1, uint32_t& r2, uint32_t& r3, uint32_t a) {
    asm volatile("ldmatrix.sync.aligned.m8n8.x4.shared.b16 {%0,%1,%2,%3},[%4];"
                 : "=r"(r0), "=r"(r1), "=r"(r2), "=r"(r3) : "r"(a));
}
__device__ __forceinline__ void ldsm_x4t(uint32_t& r0, uint32_t& r1, uint32_t& r2, uint32_t& r3, uint32_t a) {
    asm volatile("ldmatrix.sync.aligned.m8n8.x4.trans.shared.b16 {%0,%1,%2,%3},[%4];"
                 : "=r"(r0), "=r"(r1), "=r"(r2), "=r"(r3) : "r"(a));
}
__device__ __forceinline__ void ldsm_x2(uint32_t& r0, uint32_t& r1, uint32_t a) {
    asm volatile("ldmatrix.sync.aligned.m8n8.x2.shared.b16 {%0,%1},[%2];"
                 : "=r"(r0), "=r"(r1) : "r"(a));
}
__device__ __forceinline__ void mma16816(float* c, uint32_t a0, uint32_t a1, uint32_t a2, uint32_t a3,
                                         uint32_t b0, uint32_t b1) {
    asm volatile("mma.sync.aligned.m16n8k16.row.col.f32.bf16.bf16.f32 "
                 "{%0,%1,%2,%3},{%4,%5,%6,%7},{%8,%9},{%0,%1,%2,%3};"
                 : "+f"(c[0]), "+f"(c[1]), "+f"(c[2]), "+f"(c[3])
                 : "r"(a0), "r"(a1), "r"(a2), "r"(a3), "r"(b0), "r"(b1));
}
__device__ __forceinline__ void mma16832(float* c, uint32_t a0, uint32_t a1, uint32_t a2, uint32_t a3,
                                         uint32_t b0, uint32_t b1) {
    asm volatile("mma.sync.aligned.m16n8k32.row.col.f32.e4m3.e4m3.f32 "
                 "{%0,%1,%2,%3},{%4,%5,%6,%7},{%8,%9},{%0,%1,%2,%3};"
                 : "+f"(c[0]), "+f"(c[1]), "+f"(c[2]), "+f"(c[3])
                 : "r"(a0), "r"(a1), "r"(a2), "r"(a3), "r"(b0), "r"(b1));
}
__device__ __forceinline__ uint32_t f2bf2(float x, float y) {
    __nv_bfloat162 h = __float22bfloat162_rn(make_float2(x, y));
    return *reinterpret_cast<uint32_t*>(&h);
}
__device__ __forceinline__ uint32_t f2e4m3x4(float x0, float x1, float x2, float x3) {
    uint16_t lo, hi;
    asm("cvt.rn.satfinite.e4m3x2.f32 %0, %1, %2;" : "=h"(lo) : "f"(x1), "f"(x0));
    asm("cvt.rn.satfinite.e4m3x2.f32 %0, %1, %2;" : "=h"(hi) : "f"(x3), "f"(x2));
    return (uint32_t)lo | ((uint32_t)hi << 16);
}
__device__ __forceinline__ void cpasync16(uint32_t s, const void* g) {
    asm volatile("cp.async.ca.shared.global [%0],[%1],16;" :: "r"(s), "l"(g));
}
#define CP_COMMIT() asm volatile("cp.async.commit_group;" ::: "memory")
#define CP_WAIT0()  asm volatile("cp.async.wait_group 0;" ::: "memory")
#define CP_WAIT2()  asm volatile("cp.async.wait_group 2;" ::: "memory")

#define LDM  272                    // fp8 monolithic tile stride (256 + 16)
#define TILE_B (128 * LDM)          // 34816 bytes per tile
#define KQV_SMEM (2 * TILE_B)       // 69632 bytes
#define LDA  40                     // bf16 A stride
#define LDB  264                    // bf16 out_gemm B stride
#define A_ST (128 * LDA)
#define B_ST (32 * LDB)
#define OUT_SMEM ((4 * A_ST + 4 * B_ST) * 2)

// ============================================================
// prep: merged conv_w8 (blocks 0..191) + conv_xT8 (blocks 192..2239).
// ============================================================
__global__ __launch_bounds__(256) void prep(
    const float* __restrict__ x,
    const float* __restrict__ Wk, const float* __restrict__ Wq, const float* __restrict__ Wv)
{
    __shared__ float T[64][65];
    const int t = threadIdx.x;

    if (blockIdx.x < 192) {
        int e4 = blockIdx.x * 256 + t;
        int row = e4 >> 6;
        int col = (e4 & 63) * 4;
        const float* src = (row < 256) ? (Wk + (size_t)row * 256)
                         : (row < 512) ? (Wq + (size_t)(row - 256) * 256)
                                       : (Wv + (size_t)(row - 512) * 256);
        float4 v = *(const float4*)(src + col);
        *(uint32_t*)&g_Wf8[(size_t)row * 256 + col] =
            f2e4m3x4(v.x * SCALE_W, v.y * SCALE_W, v.z * SCALE_W, v.w * SCALE_W);
        return;
    }

    const int j  = blockIdx.x - 192;
    const int b  = j >> 9;
    const int rem = j & 511;
    const int c0 = (rem >> 7) * 64;
    const int s0 = (rem & 127) * 64;

    const int sc = t & 63, cr = t >> 6;
    #pragma unroll
    for (int i = 0; i < 16; i++) {
        int c = cr * 16 + i;
        T[c][sc] = x[((size_t)b * CH + c0 + c) * NTOK + s0 + sc];
    }
    __syncthreads();
    const int s = t >> 2, quarter = t & 3;
    uint32_t o[4];
    #pragma unroll
    for (int jj = 0; jj < 4; jj++) {
        int c = quarter * 16 + jj * 4;
        o[jj] = f2e4m3x4(T[c][s], T[c + 1][s], T[c + 2][s], T[c + 3][s]);
    }
    *(uint4*)&g_xT8[((size_t)b * NTOK + s0 + s) * CH + c0 + quarter * 16] =
        make_uint4(o[0], o[1], o[2], o[3]);
}

// ============================================================
// K1: kqv_gemm fp8 MONOLITHIC + in-epilogue Q softmax normalization.
// grid (64, 6, 4), 256 thr, 2 CTAs/SM.
// ============================================================
__global__ __launch_bounds__(256, 2) void kqv_gemm(
    const float* __restrict__ bk, const float* __restrict__ bq, const float* __restrict__ bv)
{
    extern __shared__ uint8_t smem[];
    uint8_t* As = smem;
    uint8_t* Bs = smem + TILE_B;

    const int b    = blockIdx.z;
    const int type = blockIdx.y >> 1;
    const int o_in = (blockIdx.y & 1) * 128;
    const int s0   = blockIdx.x * 128;
    const int tid  = threadIdx.x;

    const uint8_t* Ag = g_Wf8 + (size_t)(type * 256 + o_in) * 256;
    const uint8_t* Bg = g_xT8 + ((size_t)b * NTOK + s0) * 256;

    #pragma unroll
    for (int i = 0; i < 8; i++) {
        int task = tid + i * 256;
        int row = task >> 4, chunk = (task & 15) * 16;
        cpasync16(smem_u32(&As[row * LDM + chunk]), Ag + (size_t)row * 256 + chunk);
        cpasync16(smem_u32(&Bs[row * LDM + chunk]), Bg + (size_t)row * 256 + chunk);
    }
    CP_COMMIT();

    float acc[4][4][4];
    #pragma unroll
    for (int i = 0; i < 4; i++)
        #pragma unroll
        for (int j = 0; j < 4; j++)
            #pragma unroll
            for (int k = 0; k < 4; k++) acc[i][j][k] = 0.f;

    const int w = tid >> 5, L = tid & 31;
    const int wm = (w >> 2) * 64, wn = (w & 3) * 32;
    const int aOff = (L & 15) * LDM + (L >> 4) * 16;
    const int bRowOff = ((L >> 4) * 8 + (L & 7)) * LDM + ((L >> 3) & 1) * 16;

    CP_WAIT0();
    __syncthreads();

    #pragma unroll
    for (int kb = 0; kb < 8; kb++) {
        uint32_t af[4][4], bf[4][2];
        #pragma unroll
        for (int mi = 0; mi < 4; mi++)
            ldsm_x4(af[mi][0], af[mi][1], af[mi][2], af[mi][3],
                    smem_u32(&As[(wm + mi * 16) * LDM + kb * 32 + aOff]));
        #pragma unroll
        for (int nj = 0; nj < 2; nj++)
            ldsm_x4(bf[2 * nj][0], bf[2 * nj][1], bf[2 * nj + 1][0], bf[2 * nj + 1][1],
                    smem_u32(&Bs[(wn + nj * 16) * LDM + kb * 32 + bRowOff]));
        #pragma unroll
        for (int mi = 0; mi < 4; mi++)
            #pragma unroll
            for (int ni = 0; ni < 4; ni++)
                mma16832(acc[mi][ni], af[mi][0], af[mi][1], af[mi][2], af[mi][3],
                         bf[ni][0], bf[ni][1]);
    }

    const float* bias = (type == 0) ? bk : (type == 1) ? bq : bv;
    const int g = L >> 2, q = L & 3;
    const int orow_base = type * 256 + o_in;

    // transform acc -> output values (exp for K/Q)
    #pragma unroll
    for (int mi = 0; mi < 4; mi++) {
        const int ol = wm + mi * 16 + g;
        const float b1 = bias[o_in + ol];
        const float b2 = bias[o_in + ol + 8];
        #pragma unroll
        for (int ni = 0; ni < 4; ni++) {
            float v0 = acc[mi][ni][0] * INV_W + b1, v1 = acc[mi][ni][1] * INV_W + b1;
            float v2 = acc[mi][ni][2] * INV_W + b2, v3 = acc[mi][ni][3] * INV_W + b2;
            if (type < 2) { v0 = __expf(v0); v1 = __expf(v1); v2 = __expf(v2); v3 = __expf(v3); }
            acc[mi][ni][0] = v0; acc[mi][ni][1] = v1;
            acc[mi][ni][2] = v2; acc[mi][ni][3] = v3;
        }
    }

    // Q: normalize in place. Head = 32 consecutive o rows; for a fixed column,
    // the head's 32 rows live on the 8 lanes sharing q (bits 2..4 of L vary).
    if (type == 1) {
        #pragma unroll
        for (int t = 0; t < 2; t++) {          // head slot within the 64-row warp tile
            #pragma unroll
            for (int ni = 0; ni < 4; ni++) {
                #pragma unroll
                for (int c = 0; c < 2; c++) {  // column parity (scol / scol+1)
                    float z = acc[2 * t][ni][c] + acc[2 * t][ni][c + 2]
                            + acc[2 * t + 1][ni][c] + acc[2 * t + 1][ni][c + 2];
                    z += __shfl_xor_sync(0xFFFFFFFFu, z, 4);
                    z += __shfl_xor_sync(0xFFFFFFFFu, z, 8);
                    z += __shfl_xor_sync(0xFFFFFFFFu, z, 16);
                    const float r = 1.0f / z;
                    acc[2 * t][ni][c]         *= r;
                    acc[2 * t][ni][c + 2]     *= r;
                    acc[2 * t + 1][ni][c]     *= r;
                    acc[2 * t + 1][ni][c + 2] *= r;
                }
            }
        }
    }

    // store bf16 [row][s]
    #pragma unroll
    for (int mi = 0; mi < 4; mi++) {
        const int ol = wm + mi * 16 + g;
        #pragma unroll
        for (int ni = 0; ni < 4; ni++) {
            const int scol = s0 + wn + ni * 8 + 2 * q;
            size_t i0 = ((size_t)b * KQVROWS + orow_base + ol) * NTOK + scol;
            size_t i1 = ((size_t)b * KQVROWS + orow_base + ol + 8) * NTOK + scol;
            *reinterpret_cast<uint32_t*>(&g_kqvb[i0]) = f2bf2(acc[mi][ni][0], acc[mi][ni][1]);
            *reinterpret_cast<uint32_t*>(&g_kqvb[i1]) = f2bf2(acc[mi][ni][2], acc[mi][ni][3]);
        }
    }
}

// ============================================================
// K2: ctx partials via bf16 MMA (warp = head). grid (NSPL=64, BATCH).
// ============================================================
#define CLDA 40
__global__ __launch_bounds__(256) void ctx_mma()
{
    __shared__ __nv_bfloat16 Ke[256 * CLDA];
    __shared__ __nv_bfloat16 Vs[8 * 40 * CLDA];

    const int split = blockIdx.x, b = blockIdx.y;
    const int tid = threadIdx.x;
    const int h = tid >> 5, L = tid & 31;
    const int sbase = split * (NTOK / NSPL);

    for (int i = tid; i < 8 * 8 * CLDA; i += 256) {
        int hh = i / (8 * CLDA); int rem = i % (8 * CLDA);
        int rr = rem / CLDA; int c = rem % CLDA;
        Vs[hh * 40 * CLDA + (32 + rr) * CLDA + c] =
            (rr == 0 && c < 32) ? __float2bfloat16(1.0f) : __float2bfloat16(0.0f);
    }

    const int lRow = tid >> 1, lHalf = (tid & 1) * 16;
    const __nv_bfloat16* Kg = g_kqvb + ((size_t)b * KQVROWS) * NTOK + sbase;
    const __nv_bfloat16* Vg = g_kqvb + ((size_t)b * KQVROWS + 512) * NTOK + sbase;

    uint4 pk[2][2], pv[2][2];
    #pragma unroll
    for (int j = 0; j < 2; j++) {
        const __nv_bfloat16* kp = Kg + (size_t)(lRow + 128 * j) * NTOK + lHalf;
        const __nv_bfloat16* vp = Vg + (size_t)(lRow + 128 * j) * NTOK + lHalf;
        pk[j][0] = *(const uint4*)(kp); pk[j][1] = *(const uint4*)(kp + 8);
        pv[j][0] = *(const uint4*)(vp); pv[j][1] = *(const uint4*)(vp + 8);
    }

    float acc[2][5][4];
    #pragma unroll
    for (int i = 0; i < 2; i++)
        #pragma unroll
        for (int j = 0; j < 5; j++)
            #pragma unroll
            for (int k = 0; k < 4; k++) acc[i][j][k] = 0.f;

    const int aRowF = L & 15, aColF = (L >> 4) * 8;
    const int bRowF = L & 7, bColF = ((L >> 3) & 1) * 8;

    for (int ch = 0; ch < CCH; ch++) {
        __syncthreads();
        #pragma unroll
        for (int j = 0; j < 2; j++) {
            int row = lRow + 128 * j;
            *(uint4*)&Ke[row * CLDA + lHalf]     = pk[j][0];
            *(uint4*)&Ke[row * CLDA + lHalf + 8] = pk[j][1];
            int vh = row >> 5, vv = row & 31;
            *(uint4*)&Vs[(vh * 40 + vv) * CLDA + lHalf]     = pv[j][0];
            *(uint4*)&Vs[(vh * 40 + vv) * CLDA + lHalf + 8] = pv[j][1];
        }
        __syncthreads();
        if (ch < CCH - 1) {
            #pragma unroll
            for (int j = 0; j < 2; j++) {
                const __nv_bfloat16* kp = Kg + (size_t)(lRow + 128 * j) * NTOK + (ch + 1) * 32 + lHalf;
                const __nv_bfloat16* vp = Vg + (size_t)(lRow + 128 * j) * NTOK + (ch + 1) * 32 + lHalf;
                pk[j][0] = *(const uint4*)(kp); pk[j][1] = *(const uint4*)(kp + 8);
                pv[j][0] = *(const uint4*)(vp); pv[j][1] = *(const uint4*)(vp + 8);
            }
        }
        #pragma unroll
        for (int ks = 0; ks < 2; ks++) {
            uint32_t af[2][4], bf[5][2];
            #pragma unroll
            for (int mi = 0; mi < 2; mi++)
                ldsm_x4(af[mi][0], af[mi][1], af[mi][2], af[mi][3],
                        smem_u32(&Ke[(h * 32 + mi * 16 + aRowF) * CLDA + ks * 16 + aColF]));
            #pragma unroll
            for (int ni = 0; ni < 5; ni++)
                ldsm_x2(bf[ni][0], bf[ni][1],
                        smem_u32(&Vs[(h * 40 + ni * 8 + bRowF) * CLDA + ks * 16 + bColF]));
            #pragma unroll
            for (int mi = 0; mi < 2; mi++)
                #pragma unroll
                for (int ni = 0; ni < 5; ni++)
                    mma16816(acc[mi][ni], af[mi][0], af[mi][1], af[mi][2], af[mi][3],
                             bf[ni][0], bf[ni][1]);
        }
    }

    const int g = L >> 2, q = L & 3;
    float* cp = g_ctxp + (((size_t)(b * HEADS + h) * NSPL) + split) * 1024;
    #pragma unroll
    for (int mi = 0; mi < 2; mi++) {
        const int k0 = mi * 16 + g;
        #pragma unroll
        for (int ni = 0; ni < 4; ni++) {
            const int v = ni * 8 + 2 * q;
            *(float2*)&cp[k0 * 32 + v]       = make_float2(acc[mi][ni][0], acc[mi][ni][1]);
            *(float2*)&cp[(k0 + 8) * 32 + v] = make_float2(acc[mi][ni][2], acc[mi][ni][3]);
        }
        if (q == 0) {
            float* zp = g_zp + (((size_t)(b * HEADS + h) * NSPL) + split) * 32;
            zp[k0]     = acc[mi][4][0];
            zp[k0 + 8] = acc[mi][4][2];
        }
    }
}

// ============================================================
// make_M: fused reduce + Wr fold -> bf16. grid 32 (b*8+h), 256 thr.
// ============================================================
__global__ __launch_bounds__(256) void make_M(const float* __restrict__ Wr)
{
    const int bh = blockIdx.x;
    const int b = bh >> 3, h = bh & 7;
    __shared__ float ctxs[32][33];
    __shared__ float zinv[32];
    const int tid = threadIdx.x;

    if (tid < 32) {
        float z = 0.f;
        for (int sp = 0; sp < NSPL; sp++)
            z += g_zp[((size_t)bh * NSPL + sp) * 32 + tid];
        zinv[tid] = 1.0f / z;
    }
    __syncthreads();

    for (int i = tid; i < 1024; i += 256) {
        int k = i >> 5;
        float ssum = 0.f;
        for (int sp = 0; sp < NSPL; sp++)
            ssum += g_ctxp[((size_t)bh * NSPL + sp) * 1024 + i];
        ctxs[k][i & 31] = ssum * zinv[k];
    }
    __syncthreads();

    const int o = tid;
    float wr[32];
    const float* wrow = Wr + (size_t)o * 256 + h * 32;
    #pragma unroll
    for (int v = 0; v < 32; v += 4) {
        float4 t4 = *(const float4*)(wrow + v);
        wr[v] = t4.x; wr[v + 1] = t4.y; wr[v + 2] = t4.z; wr[v + 3] = t4.w;
    }
    uint32_t packed[16];
    #pragma unroll
    for (int kp = 0; kp < 16; kp++) {
        float r[2];
        #pragma unroll
        for (int half = 0; half < 2; half++) {
            const int k = kp * 2 + half;
            float a = 0.f;
            #pragma unroll
            for (int v = 0; v < 32; v++) a += wr[v] * ctxs[k][v];
            r[half] = a;
        }
        packed[kp] = f2bf2(r[0], r[1]);
    }
    uint4* dst = (uint4*)&g_Mbf[((size_t)b * CH + o) * CH + h * 32];
    #pragma unroll
    for (int i = 0; i < 4; i++)
        dst[i] = make_uint4(packed[4 * i], packed[4 * i + 1], packed[4 * i + 2], packed[4 * i + 3]);
}

// ============================================================
// out_gemm: bf16, CTA 128x256, warp 64x64, 4-stage cp.async (proven).
// ============================================================
__global__ __launch_bounds__(256, 1) void out_gemm(
    const float* __restrict__ x, const float* __restrict__ br,
    float* __restrict__ out)
{
    extern __shared__ char smemc[];
    __nv_bfloat16* As = (__nv_bfloat16*)smemc;
    __nv_bfloat16* Bs = (__nv_bfloat16*)smemc + 4 * A_ST;

    const int b  = blockIdx.z;
    const int o0 = blockIdx.y * 128;
    const int s0 = blockIdx.x * 256;
    const int tid = threadIdx.x;

    const __nv_bfloat16* Ag = g_Mbf + ((size_t)b * CH + o0) * CH;
    const __nv_bfloat16* Bg = g_kqvb + ((size_t)b * KQVROWS + 256) * NTOK + s0;

    auto load_stage = [&](int kb, int st) {
        #pragma unroll
        for (int i = 0; i < 2; i++) {
            int task = tid + i * 256;
            int row = task >> 2, col = (task & 3) * 8;
            cpasync16(smem_u32(&As[st * A_ST + row * LDA + col]),
                      Ag + (size_t)row * 256 + kb * 32 + col);
        }
        #pragma unroll
        for (int i = 0; i < 4; i++) {
            int task = tid + i * 256;
            int row = task >> 5, col = (task & 31) * 8;
            cpasync16(smem_u32(&Bs[st * B_ST + row * LDB + col]),
                      Bg + (size_t)(kb * 32 + row) * NTOK + col);
        }
    };

    float acc[4][8][4];
    #pragma unroll
    for (int i = 0; i < 4; i++)
        #pragma unroll
        for (int j = 0; j < 8; j++)
            #pragma unroll
            for (int k = 0; k < 4; k++) acc[i][j][k] = 0.f;

    const int w = tid >> 5, L = tid & 31;
    const int wm = (w >> 2) * 64, wn = (w & 3) * 64;
    const int aRowF = L & 15, aColF = (L >> 4) * 8;
    const int bkRow = L & 15, bnSel = L >> 4;

    load_stage(0, 0); CP_COMMIT();
    load_stage(1, 1); CP_COMMIT();
    load_stage(2, 2); CP_COMMIT();

    for (int kb = 0; kb < 8; kb++) {
        CP_WAIT2();
        __syncthreads();
        const int nk = kb + 3;
        if (nk < 8) load_stage(nk, nk & 3);
        CP_COMMIT();
        const int st = kb & 3;
        #pragma unroll
        for (int ks = 0; ks < 2; ks++) {
            uint32_t af[4][4], bf[8][2];
            #pragma unroll
            for (int mi = 0; mi < 4; mi++)
                ldsm_x4(af[mi][0], af[mi][1], af[mi][2], af[mi][3],
                        smem_u32(&As[st * A_ST + (wm + mi * 16 + aRowF) * LDA + ks * 16 + aColF]));
            #pragma unroll
            for (int nj = 0; nj < 4; nj++)
                ldsm_x4t(bf[2 * nj][0], bf[2 * nj][1], bf[2 * nj + 1][0], bf[2 * nj + 1][1],
                         smem_u32(&Bs[st * B_ST + (ks * 16 + bkRow) * LDB + wn + (nj * 2 + bnSel) * 8]));
            #pragma unroll
            for (int mi = 0; mi < 4; mi++)
                #pragma unroll
                for (int ni = 0; ni < 8; ni++)
                    mma16816(acc[mi][ni], af[mi][0], af[mi][1], af[mi][2], af[mi][3],
                             bf[ni][0], bf[ni][1]);
        }
    }

    const int g = L >> 2, q = L & 3;
    #pragma unroll
    for (int mi = 0; mi < 4; mi++) {
        const int o1 = o0 + wm + mi * 16 + g;
        const int o2 = o1 + 8;
        const float b1 = br[o1], b2 = br[o2];
        #pragma unroll
        for (int ni = 0; ni < 8; ni++) {
            const int s = s0 + wn + ni * 8 + 2 * q;
            float2 x1 = *(const float2*)&x[((size_t)b * CH + o1) * NTOK + s];
            float2 x2 = *(const float2*)&x[((size_t)b * CH + o2) * NTOK + s];
            out[((size_t)b * NTOK + s) * CH + o1]     = acc[mi][ni][0] + b1 + x1.x;
            out[((size_t)b * NTOK + s + 1) * CH + o1] = acc[mi][ni][1] + b1 + x1.y;
            out[((size_t)b * NTOK + s) * CH + o2]     = acc[mi][ni][2] + b2 + x2.x;
            out[((size_t)b * NTOK + s + 1) * CH + o2] = acc[mi][ni][3] + b2 + x2.y;
        }
    }
}

// ============================================================
extern "C" void kernel_launch(void* const* d_in, const int* in_sizes, int n_in,
                              void* d_out, int out_size)
{
    const float* x  = (const float*)d_in[0];
    const float* Wk = (const float*)d_in[1];
    const float* bk = (const float*)d_in[2];
    const float* Wq = (const float*)d_in[3];
    const float* bq = (const float*)d_in[4];
    const float* Wv = (const float*)d_in[5];
    const float* bv = (const float*)d_in[6];
    const float* Wr = (const float*)d_in[7];
    const float* br = (const float*)d_in[8];
    float* out = (float*)d_out;

    cudaFuncSetAttribute(kqv_gemm, cudaFuncAttributeMaxDynamicSharedMemorySize, KQV_SMEM);
    cudaFuncSetAttribute(out_gemm, cudaFuncAttributeMaxDynamicSharedMemorySize, OUT_SMEM);

    prep<<<2240, 256>>>(x, Wk, Wq, Wv);                          // #1
    kqv_gemm<<<dim3(64, 6, 4), 256, KQV_SMEM>>>(bk, bq, bv);     // #2
    ctx_mma<<<dim3(NSPL, BATCH), 256>>>();                       // #3
    make_M<<<32, 256>>>(Wr);                                     // #4  <- ncu target
    out_gemm<<<dim3(32, 2, 4), 256, OUT_SMEM>>>(x, br, out);     // #5
}

// round 15
// speedup vs baseline: 1.0763x; 1.0763x over previous
#include <cuda_runtime.h>
#include <cuda_bf16.h>
#include <math.h>
#include <stdint.h>

#define BATCH   4
#define NTOK    8192
#define CH      256
#define HEADS   8
#define KQVROWS 768
#define NSPL    64
#define CCH     (NTOK / NSPL / 32)

#define SCALE_W 32.0f
#define INV_W   (1.0f / 32.0f)

// ---------------- scratch ----------------
__device__ uint8_t g_Wf8[KQVROWS * CH];                          // fp8 [Wk;Wq;Wv] * 32
__device__ uint8_t g_xT8[(size_t)BATCH * NTOK * CH];             // fp8 x^T [b][s][c]
__device__ __nv_bfloat16 g_kqvb[(size_t)BATCH * KQVROWS * NTOK]; // expK(0..255) expQ->Qn(256..511) V(512..767)
__device__ float g_ctxp[BATCH * HEADS * NSPL * 32 * 32];
__device__ float g_zp[BATCH * HEADS * NSPL * 32];
__device__ __nv_bfloat16 g_Mbf[BATCH * CH * CH];

// ---------------- helpers ----------------
__device__ __forceinline__ uint32_t smem_u32(const void* p) {
    return (uint32_t)__cvta_generic_to_shared(p);
}
__device__ __forceinline__ void ldsm_x4(uint32_t& r0, uint32_t& r1, uint32_t& r2, uint32_t& r3, uint32_t a) {
    asm volatile("ldmatrix.sync.aligned.m8n8.x4.shared.b16 {%0,%1,%2,%3},[%4];"
                 : "=r"(r0), "=r"(r1), "=r"(r2), "=r"(r3) : "r"(a));
}
__device__ __forceinline__ void ldsm_x4t(uint32_t& r0, uint32_t& r1, uint32_t& r2, uint32_t& r3, uint32_t a) {
    asm volatile("ldmatrix.sync.aligned.m8n8.x4.trans.shared.b16 {%0,%1,%2,%3},[%4];"
                 : "=r"(r0), "=r"(r1), "=r"(r2), "=r"(r3) : "r"(a));
}
__device__ __forceinline__ void ldsm_x2(uint32_t& r0, uint32_t& r1, uint32_t a) {
    asm volatile("ldmatrix.sync.aligned.m8n8.x2.shared.b16 {%0,%1},[%2];"
                 : "=r"(r0), "=r"(r1) : "r"(a));
}
__device__ __forceinline__ void mma16816(float* c, uint32_t a0, uint32_t a1, uint32_t a2, uint32_t a3,
                                         uint32_t b0, uint32_t b1) {
    asm volatile("mma.sync.aligned.m16n8k16.row.col.f32.bf16.bf16.f32 "
                 "{%0,%1,%2,%3},{%4,%5,%6,%7},{%8,%9},{%0,%1,%2,%3};"
                 : "+f"(c[0]), "+f"(c[1]), "+f"(c[2]), "+f"(c[3])
                 : "r"(a0), "r"(a1), "r"(a2), "r"(a3), "r"(b0), "r"(b1));
}
__device__ __forceinline__ void mma16832(float* c, uint32_t a0, uint32_t a1, uint32_t a2, uint32_t a3,
                                         uint32_t b0, uint32_t b1) {
    asm volatile("mma.sync.aligned.m16n8k32.row.col.f32.e4m3.e4m3.f32 "
                 "{%0,%1,%2,%3},{%4,%5,%6,%7},{%8,%9},{%0,%1,%2,%3};"
                 : "+f"(c[0]), "+f"(c[1]), "+f"(c[2]), "+f"(c[3])
                 : "r"(a0), "r"(a1), "r"(a2), "r"(a3), "r"(b0), "r"(b1));
}
__device__ __forceinline__ uint32_t f2bf2(float x, float y) {
    __nv_bfloat162 h = __float22bfloat162_rn(make_float2(x, y));
    return *reinterpret_cast<uint32_t*>(&h);
}
__device__ __forceinline__ uint32_t f2e4m3x4(float x0, float x1, float x2, float x3) {
    uint16_t lo, hi;
    asm("cvt.rn.satfinite.e4m3x2.f32 %0, %1, %2;" : "=h"(lo) : "f"(x1), "f"(x0));
    asm("cvt.rn.satfinite.e4m3x2.f32 %0, %1, %2;" : "=h"(hi) : "f"(x3), "f"(x2));
    return (uint32_t)lo | ((uint32_t)hi << 16);
}
__device__ __forceinline__ void cpasync16(uint32_t s, const void* g) {
    asm volatile("cp.async.ca.shared.global [%0],[%1],16;" :: "r"(s), "l"(g));
}
#define CP_COMMIT() asm volatile("cp.async.commit_group;" ::: "memory")
#define CP_WAIT0()  asm volatile("cp.async.wait_group 0;" ::: "memory")
#define CP_WAIT2()  asm volatile("cp.async.wait_group 2;" ::: "memory")

#define LDM  272                    // fp8 monolithic tile stride (256 + 16)
#define TILE_B (128 * LDM)          // 34816 bytes per tile
#define KQV_SMEM (2 * TILE_B)       // 69632 bytes
#define LDA  40                     // bf16 A stride
#define LDB  264                    // bf16 out_gemm B stride
#define A_ST (128 * LDA)
#define B_ST (32 * LDB)
#define OUT_SMEM ((4 * A_ST + 4 * B_ST) * 2)

// ============================================================
// prep: merged conv_w8 (blocks 0..191) + conv_xT8 (blocks 192..2239).
// ============================================================
__global__ __launch_bounds__(256) void prep(
    const float* __restrict__ x,
    const float* __restrict__ Wk, const float* __restrict__ Wq, const float* __restrict__ Wv)
{
    __shared__ float T[64][65];
    const int t = threadIdx.x;

    if (blockIdx.x < 192) {
        int e4 = blockIdx.x * 256 + t;
        int row = e4 >> 6;
        int col = (e4 & 63) * 4;
        const float* src = (row < 256) ? (Wk + (size_t)row * 256)
                         : (row < 512) ? (Wq + (size_t)(row - 256) * 256)
                                       : (Wv + (size_t)(row - 512) * 256);
        float4 v = *(const float4*)(src + col);
        *(uint32_t*)&g_Wf8[(size_t)row * 256 + col] =
            f2e4m3x4(v.x * SCALE_W, v.y * SCALE_W, v.z * SCALE_W, v.w * SCALE_W);
        return;
    }

    const int j  = blockIdx.x - 192;
    const int b  = j >> 9;
    const int rem = j & 511;
    const int c0 = (rem >> 7) * 64;
    const int s0 = (rem & 127) * 64;

    const int sc = t & 63, cr = t >> 6;
    #pragma unroll
    for (int i = 0; i < 16; i++) {
        int c = cr * 16 + i;
        T[c][sc] = x[((size_t)b * CH + c0 + c) * NTOK + s0 + sc];
    }
    __syncthreads();
    const int s = t >> 2, quarter = t & 3;
    uint32_t o[4];
    #pragma unroll
    for (int jj = 0; jj < 4; jj++) {
        int c = quarter * 16 + jj * 4;
        o[jj] = f2e4m3x4(T[c][s], T[c + 1][s], T[c + 2][s], T[c + 3][s]);
    }
    *(uint4*)&g_xT8[((size_t)b * NTOK + s0 + s) * CH + c0 + quarter * 16] =
        make_uint4(o[0], o[1], o[2], o[3]);
}

// ============================================================
// K1: kqv_gemm fp8 MONOLITHIC (R11/R13 winner, byte-identical).
// grid (64, 6, 4), 256 thr, 2 CTAs/SM.
// ============================================================
__global__ __launch_bounds__(256, 2) void kqv_gemm(
    const float* __restrict__ bk, const float* __restrict__ bq, const float* __restrict__ bv)
{
    extern __shared__ uint8_t smem[];
    uint8_t* As = smem;
    uint8_t* Bs = smem + TILE_B;

    const int b    = blockIdx.z;
    const int type = blockIdx.y >> 1;
    const int o_in = (blockIdx.y & 1) * 128;
    const int s0   = blockIdx.x * 128;
    const int tid  = threadIdx.x;

    const uint8_t* Ag = g_Wf8 + (size_t)(type * 256 + o_in) * 256;
    const uint8_t* Bg = g_xT8 + ((size_t)b * NTOK + s0) * 256;

    #pragma unroll
    for (int i = 0; i < 8; i++) {
        int task = tid + i * 256;
        int row = task >> 4, chunk = (task & 15) * 16;
        cpasync16(smem_u32(&As[row * LDM + chunk]), Ag + (size_t)row * 256 + chunk);
        cpasync16(smem_u32(&Bs[row * LDM + chunk]), Bg + (size_t)row * 256 + chunk);
    }
    CP_COMMIT();

    float acc[4][4][4];
    #pragma unroll
    for (int i = 0; i < 4; i++)
        #pragma unroll
        for (int j = 0; j < 4; j++)
            #pragma unroll
            for (int k = 0; k < 4; k++) acc[i][j][k] = 0.f;

    const int w = tid >> 5, L = tid & 31;
    const int wm = (w >> 2) * 64, wn = (w & 3) * 32;
    const int aOff = (L & 15) * LDM + (L >> 4) * 16;
    const int bRowOff = ((L >> 4) * 8 + (L & 7)) * LDM + ((L >> 3) & 1) * 16;

    CP_WAIT0();
    __syncthreads();

    #pragma unroll
    for (int kb = 0; kb < 8; kb++) {
        uint32_t af[4][4], bf[4][2];
        #pragma unroll
        for (int mi = 0; mi < 4; mi++)
            ldsm_x4(af[mi][0], af[mi][1], af[mi][2], af[mi][3],
                    smem_u32(&As[(wm + mi * 16) * LDM + kb * 32 + aOff]));
        #pragma unroll
        for (int nj = 0; nj < 2; nj++)
            ldsm_x4(bf[2 * nj][0], bf[2 * nj][1], bf[2 * nj + 1][0], bf[2 * nj + 1][1],
                    smem_u32(&Bs[(wn + nj * 16) * LDM + kb * 32 + bRowOff]));
        #pragma unroll
        for (int mi = 0; mi < 4; mi++)
            #pragma unroll
            for (int ni = 0; ni < 4; ni++)
                mma16832(acc[mi][ni], af[mi][0], af[mi][1], af[mi][2], af[mi][3],
                         bf[ni][0], bf[ni][1]);
    }

    const float* bias = (type == 0) ? bk : (type == 1) ? bq : bv;
    const int g = L >> 2, q = L & 3;
    const bool doExp = (type < 2);
    const int orow_base = type * 256 + o_in;
    #pragma unroll
    for (int mi = 0; mi < 4; mi++) {
        const int ol = wm + mi * 16 + g;
        const float b1 = bias[o_in + ol];
        const float b2 = bias[o_in + ol + 8];
        #pragma unroll
        for (int ni = 0; ni < 4; ni++) {
            float v0 = acc[mi][ni][0] * INV_W + b1, v1 = acc[mi][ni][1] * INV_W + b1;
            float v2 = acc[mi][ni][2] * INV_W + b2, v3 = acc[mi][ni][3] * INV_W + b2;
            if (doExp) { v0 = __expf(v0); v1 = __expf(v1); v2 = __expf(v2); v3 = __expf(v3); }
            const int scol = s0 + wn + ni * 8 + 2 * q;
            size_t i0 = ((size_t)b * KQVROWS + orow_base + ol) * NTOK + scol;
            size_t i1 = ((size_t)b * KQVROWS + orow_base + ol + 8) * NTOK + scol;
            *reinterpret_cast<uint32_t*>(&g_kqvb[i0]) = f2bf2(v0, v1);
            *reinterpret_cast<uint32_t*>(&g_kqvb[i1]) = f2bf2(v2, v3);
        }
    }
}

// ============================================================
// K2: ctx partials via bf16 MMA (warp = head). grid (NSPL=64, BATCH).
// ============================================================
#define CLDA 40
__global__ __launch_bounds__(256) void ctx_mma()
{
    __shared__ __nv_bfloat16 Ke[256 * CLDA];
    __shared__ __nv_bfloat16 Vs[8 * 40 * CLDA];

    const int split = blockIdx.x, b = blockIdx.y;
    const int tid = threadIdx.x;
    const int h = tid >> 5, L = tid & 31;
    const int sbase = split * (NTOK / NSPL);

    for (int i = tid; i < 8 * 8 * CLDA; i += 256) {
        int hh = i / (8 * CLDA); int rem = i % (8 * CLDA);
        int rr = rem / CLDA; int c = rem % CLDA;
        Vs[hh * 40 * CLDA + (32 + rr) * CLDA + c] =
            (rr == 0 && c < 32) ? __float2bfloat16(1.0f) : __float2bfloat16(0.0f);
    }

    const int lRow = tid >> 1, lHalf = (tid & 1) * 16;
    const __nv_bfloat16* Kg = g_kqvb + ((size_t)b * KQVROWS) * NTOK + sbase;
    const __nv_bfloat16* Vg = g_kqvb + ((size_t)b * KQVROWS + 512) * NTOK + sbase;

    uint4 pk[2][2], pv[2][2];
    #pragma unroll
    for (int j = 0; j < 2; j++) {
        const __nv_bfloat16* kp = Kg + (size_t)(lRow + 128 * j) * NTOK + lHalf;
        const __nv_bfloat16* vp = Vg + (size_t)(lRow + 128 * j) * NTOK + lHalf;
        pk[j][0] = *(const uint4*)(kp); pk[j][1] = *(const uint4*)(kp + 8);
        pv[j][0] = *(const uint4*)(vp); pv[j][1] = *(const uint4*)(vp + 8);
    }

    float acc[2][5][4];
    #pragma unroll
    for (int i = 0; i < 2; i++)
        #pragma unroll
        for (int j = 0; j < 5; j++)
            #pragma unroll
            for (int k = 0; k < 4; k++) acc[i][j][k] = 0.f;

    const int aRowF = L & 15, aColF = (L >> 4) * 8;
    const int bRowF = L & 7, bColF = ((L >> 3) & 1) * 8;

    for (int ch = 0; ch < CCH; ch++) {
        __syncthreads();
        #pragma unroll
        for (int j = 0; j < 2; j++) {
            int row = lRow + 128 * j;
            *(uint4*)&Ke[row * CLDA + lHalf]     = pk[j][0];
            *(uint4*)&Ke[row * CLDA + lHalf + 8] = pk[j][1];
            int vh = row >> 5, vv = row & 31;
            *(uint4*)&Vs[(vh * 40 + vv) * CLDA + lHalf]     = pv[j][0];
            *(uint4*)&Vs[(vh * 40 + vv) * CLDA + lHalf + 8] = pv[j][1];
        }
        __syncthreads();
        if (ch < CCH - 1) {
            #pragma unroll
            for (int j = 0; j < 2; j++) {
                const __nv_bfloat16* kp = Kg + (size_t)(lRow + 128 * j) * NTOK + (ch + 1) * 32 + lHalf;
                const __nv_bfloat16* vp = Vg + (size_t)(lRow + 128 * j) * NTOK + (ch + 1) * 32 + lHalf;
                pk[j][0] = *(const uint4*)(kp); pk[j][1] = *(const uint4*)(kp + 8);
                pv[j][0] = *(const uint4*)(vp); pv[j][1] = *(const uint4*)(vp + 8);
            }
        }
        #pragma unroll
        for (int ks = 0; ks < 2; ks++) {
            uint32_t af[2][4], bf[5][2];
            #pragma unroll
            for (int mi = 0; mi < 2; mi++)
                ldsm_x4(af[mi][0], af[mi][1], af[mi][2], af[mi][3],
                        smem_u32(&Ke[(h * 32 + mi * 16 + aRowF) * CLDA + ks * 16 + aColF]));
            #pragma unroll
            for (int ni = 0; ni < 5; ni++)
                ldsm_x2(bf[ni][0], bf[ni][1],
                        smem_u32(&Vs[(h * 40 + ni * 8 + bRowF) * CLDA + ks * 16 + bColF]));
            #pragma unroll
            for (int mi = 0; mi < 2; mi++)
                #pragma unroll
                for (int ni = 0; ni < 5; ni++)
                    mma16816(acc[mi][ni], af[mi][0], af[mi][1], af[mi][2], af[mi][3],
                             bf[ni][0], bf[ni][1]);
        }
    }

    const int g = L >> 2, q = L & 3;
    float* cp = g_ctxp + (((size_t)(b * HEADS + h) * NSPL) + split) * 1024;
    #pragma unroll
    for (int mi = 0; mi < 2; mi++) {
        const int k0 = mi * 16 + g;
        #pragma unroll
        for (int ni = 0; ni < 4; ni++) {
            const int v = ni * 8 + 2 * q;
            *(float2*)&cp[k0 * 32 + v]       = make_float2(acc[mi][ni][0], acc[mi][ni][1]);
            *(float2*)&cp[(k0 + 8) * 32 + v] = make_float2(acc[mi][ni][2], acc[mi][ni][3]);
        }
        if (q == 0) {
            float* zp = g_zp + (((size_t)(b * HEADS + h) * NSPL) + split) * 32;
            zp[k0]     = acc[mi][4][0];
            zp[k0 + 8] = acc[mi][4][2];
        }
    }
}

// ============================================================
// mkM_qsum v2:
//   blocks 0..255   : make_M, split by (bh, og) — 8 blocks per bh share the
//                     partials read through L2; each folds 32 o-rows.
//   blocks 256..767 : qsum, 2 tokens/thread via bf16x2 (full-line coalescing).
// ============================================================
__global__ __launch_bounds__(256) void mkM_qsum(const float* __restrict__ Wr)
{
    const int tid = threadIdx.x;

    if (blockIdx.x < 256) {
        // ---- make_M ----
        __shared__ float ctxs[32][33];
        __shared__ float zinv[32];
        const int bh = blockIdx.x >> 3, og = blockIdx.x & 7;
        const int b = bh >> 3, h = bh & 7;

        if (tid < 32) {
            float z = 0.f;
            for (int sp = 0; sp < NSPL; sp++)
                z += g_zp[((size_t)bh * NSPL + sp) * 32 + tid];
            zinv[tid] = 1.0f / z;
        }
        __syncthreads();

        for (int i = tid; i < 1024; i += 256) {
            int k = i >> 5;
            float ssum = 0.f;
            for (int sp = 0; sp < NSPL; sp++)
                ssum += g_ctxp[((size_t)bh * NSPL + sp) * 1024 + i];
            ctxs[k][i & 31] = ssum * zinv[k];
        }
        __syncthreads();

        // fold: 32 o-rows, 8 threads per row, 4 k each
        const int o = og * 32 + (tid >> 3);
        const int kq = tid & 7;
        float wr[32];
        const float* wrow = Wr + (size_t)o * 256 + h * 32;
        #pragma unroll
        for (int v = 0; v < 32; v += 4) {
            float4 t4 = *(const float4*)(wrow + v);
            wr[v] = t4.x; wr[v + 1] = t4.y; wr[v + 2] = t4.z; wr[v + 3] = t4.w;
        }
        float r[4];
        #pragma unroll
        for (int kk = 0; kk < 4; kk++) {
            const int k = kq * 4 + kk;
            float a = 0.f;
            #pragma unroll
            for (int v = 0; v < 32; v++) a += wr[v] * ctxs[k][v];
            r[kk] = a;
        }
        *(uint2*)&g_Mbf[((size_t)b * CH + o) * CH + h * 32 + kq * 4] =
            make_uint2(f2bf2(r[0], r[1]), f2bf2(r[2], r[3]));
        return;
    }

    // ---- qsum: 2 tokens per thread ----
    const int j = blockIdx.x - 256;          // [0, 512)
    const int b = j >> 7;                    // 128 blocks per batch
    const int h = (j >> 4) & 7;
    const int p = (j & 15) * 256 + tid;      // pair index [0, 4096)
    uint32_t* Qg = (uint32_t*)(g_kqvb + ((size_t)b * KQVROWS + 256 + h * 32) * NTOK) + p;
    uint32_t v[32];
    float s0 = 0.f, s1 = 0.f;
    #pragma unroll
    for (int k = 0; k < 32; k++) {
        v[k] = Qg[(size_t)k * (NTOK / 2)];
        __nv_bfloat162 h2 = *reinterpret_cast<const __nv_bfloat162*>(&v[k]);
        s0 += __bfloat162float(h2.x);
        s1 += __bfloat162float(h2.y);
    }
    const float r0 = 1.0f / s0, r1 = 1.0f / s1;
    #pragma unroll
    for (int k = 0; k < 32; k++) {
        __nv_bfloat162 h2 = *reinterpret_cast<const __nv_bfloat162*>(&v[k]);
        Qg[(size_t)k * (NTOK / 2)] = f2bf2(__bfloat162float(h2.x) * r0,
                                           __bfloat162float(h2.y) * r1);
    }
}

// ============================================================
// out_gemm: bf16, CTA 128x256, warp 64x64, 4-stage cp.async (R13 proven).
// ============================================================
__global__ __launch_bounds__(256, 1) void out_gemm(
    const float* __restrict__ x, const float* __restrict__ br,
    float* __restrict__ out)
{
    extern __shared__ char smemc[];
    __nv_bfloat16* As = (__nv_bfloat16*)smemc;
    __nv_bfloat16* Bs = (__nv_bfloat16*)smemc + 4 * A_ST;

    const int b  = blockIdx.z;
    const int o0 = blockIdx.y * 128;
    const int s0 = blockIdx.x * 256;
    const int tid = threadIdx.x;

    const __nv_bfloat16* Ag = g_Mbf + ((size_t)b * CH + o0) * CH;
    const __nv_bfloat16* Bg = g_kqvb + ((size_t)b * KQVROWS + 256) * NTOK + s0;

    auto load_stage = [&](int kb, int st) {
        #pragma unroll
        for (int i = 0; i < 2; i++) {
            int task = tid + i * 256;
            int row = task >> 2, col = (task & 3) * 8;
            cpasync16(smem_u32(&As[st * A_ST + row * LDA + col]),
                      Ag + (size_t)row * 256 + kb * 32 + col);
        }
        #pragma unroll
        for (int i = 0; i < 4; i++) {
            int task = tid + i * 256;
            int row = task >> 5, col = (task & 31) * 8;
            cpasync16(smem_u32(&Bs[st * B_ST + row * LDB + col]),
                      Bg + (size_t)(kb * 32 + row) * NTOK + col);
        }
    };

    float acc[4][8][4];
    #pragma unroll
    for (int i = 0; i < 4; i++)
        #pragma unroll
        for (int j = 0; j < 8; j++)
            #pragma unroll
            for (int k = 0; k < 4; k++) acc[i][j][k] = 0.f;

    const int w = tid >> 5, L = tid & 31;
    const int wm = (w >> 2) * 64, wn = (w & 3) * 64;
    const int aRowF = L & 15, aColF = (L >> 4) * 8;
    const int bkRow = L & 15, bnSel = L >> 4;

    load_stage(0, 0); CP_COMMIT();
    load_stage(1, 1); CP_COMMIT();
    load_stage(2, 2); CP_COMMIT();

    for (int kb = 0; kb < 8; kb++) {
        CP_WAIT2();
        __syncthreads();
        const int nk = kb + 3;
        if (nk < 8) load_stage(nk, nk & 3);
        CP_COMMIT();
        const int st = kb & 3;
        #pragma unroll
        for (int ks = 0; ks < 2; ks++) {
            uint32_t af[4][4], bf[8][2];
            #pragma unroll
            for (int mi = 0; mi < 4; mi++)
                ldsm_x4(af[mi][0], af[mi][1], af[mi][2], af[mi][3],
                        smem_u32(&As[st * A_ST + (wm + mi * 16 + aRowF) * LDA + ks * 16 + aColF]));
            #pragma unroll
            for (int nj = 0; nj < 4; nj++)
                ldsm_x4t(bf[2 * nj][0], bf[2 * nj][1], bf[2 * nj + 1][0], bf[2 * nj + 1][1],
                         smem_u32(&Bs[st * B_ST + (ks * 16 + bkRow) * LDB + wn + (nj * 2 + bnSel) * 8]));
            #pragma unroll
            for (int mi = 0; mi < 4; mi++)
                #pragma unroll
                for (int ni = 0; ni < 8; ni++)
                    mma16816(acc[mi][ni], af[mi][0], af[mi][1], af[mi][2], af[mi][3],
                             bf[ni][0], bf[ni][1]);
        }
    }

    const int g = L >> 2, q = L & 3;
    #pragma unroll
    for (int mi = 0; mi < 4; mi++) {
        const int o1 = o0 + wm + mi * 16 + g;
        const int o2 = o1 + 8;
        const float b1 = br[o1], b2 = br[o2];
        #pragma unroll
        for (int ni = 0; ni < 8; ni++) {
            const int s = s0 + wn + ni * 8 + 2 * q;
            float2 x1 = *(const float2*)&x[((size_t)b * CH + o1) * NTOK + s];
            float2 x2 = *(const float2*)&x[((size_t)b * CH + o2) * NTOK + s];
            out[((size_t)b * NTOK + s) * CH + o1]     = acc[mi][ni][0] + b1 + x1.x;
            out[((size_t)b * NTOK + s + 1) * CH + o1] = acc[mi][ni][1] + b1 + x1.y;
            out[((size_t)b * NTOK + s) * CH + o2]     = acc[mi][ni][2] + b2 + x2.x;
            out[((size_t)b * NTOK + s + 1) * CH + o2] = acc[mi][ni][3] + b2 + x2.y;
        }
    }
}

// ============================================================
extern "C" void kernel_launch(void* const* d_in, const int* in_sizes, int n_in,
                              void* d_out, int out_size)
{
    const float* x  = (const float*)d_in[0];
    const float* Wk = (const float*)d_in[1];
    const float* bk = (const float*)d_in[2];
    const float* Wq = (const float*)d_in[3];
    const float* bq = (const float*)d_in[4];
    const float* Wv = (const float*)d_in[5];
    const float* bv = (const float*)d_in[6];
    const float* Wr = (const float*)d_in[7];
    const float* br = (const float*)d_in[8];
    float* out = (float*)d_out;

    cudaFuncSetAttribute(kqv_gemm, cudaFuncAttributeMaxDynamicSharedMemorySize, KQV_SMEM);
    cudaFuncSetAttribute(out_gemm, cudaFuncAttributeMaxDynamicSharedMemorySize, OUT_SMEM);

    prep<<<2240, 256>>>(x, Wk, Wq, Wv);                          // #1
    kqv_gemm<<<dim3(64, 6, 4), 256, KQV_SMEM>>>(bk, bq, bv);     // #2
    ctx_mma<<<dim3(NSPL, BATCH), 256>>>();                       // #3
    mkM_qsum<<<768, 256>>>(Wr);                                  // #4  <- ncu target
    out_gemm<<<dim3(32, 2, 4), 256, OUT_SMEM>>>(x, br, out);     // #5
}